// round 15
// baseline (speedup 1.0000x reference)
#include <cuda_runtime.h>

#define NB 512
#define ND 128
#define NS 50
#define NT 32
#define NHOOPS 2
#define NL 64
#define NCLIP 50
#define NFR 10000

// ---- scratch (static device globals; no runtime allocation) ----
__device__ float g_mem[NB * ND];            // [B, D] (fused kernel -> k_final)
__device__ float g_item[NB * NL];           // [B, L]

// ============================================================================
// Fused kernel: per-b init + HOOPS × (word attention + sentence attention).
// One block per b, 256 threads (8 warps). All intermediates in SMEM:
//   s_sent[50][128] (25.6 KB), s_mem[128], s_sw/s_st[50], s_item[64].
// Word phase: warp-per-sentence, half-warp-per-row, un-shifted softmax
// (scores are O(0.01); softmax is shift-invariant), unroll 8 (R13 lesson:
// load depth > occupancy). 6 blocks/SM resident -> whole grid in one wave.
// ============================================================================
__global__ void __launch_bounds__(256, 6)
k_hoops(const int* __restrict__ user_idx,
        const int* __restrict__ item_idx,
        const float* __restrict__ emb_item,
        const float* __restrict__ W_mem,
        const float* __restrict__ b_mem,
        const int* __restrict__ uti,
        const float* __restrict__ emb_word,
        const float* __restrict__ w_word,
        const float* __restrict__ b_word,
        const float* __restrict__ w_sent,
        const float* __restrict__ b_sent) {
    int b = blockIdx.x;
    int tid = threadIdx.x, lane = tid & 31, warp = tid >> 5;

    __shared__ __align__(16) float s_sent[NS * ND];   // 25.6 KB
    __shared__ __align__(16) float s_mem[ND];
    __shared__ float s_sw[NS], s_st[NS];
    __shared__ float s_item[NL];

    // ---- init: item gather + mem = item_emb @ W_mem + b_mem ----
    int it = item_idx[b];
    if (tid < NL) {
        float v = emb_item[(size_t)it * NL + tid];
        s_item[tid] = v;
        g_item[b * NL + tid] = v;
    }
    __syncthreads();
    if (tid < ND) {
        float acc = b_mem[tid];
#pragma unroll
        for (int l = 0; l < NL; l++) acc += s_item[l] * W_mem[l * ND + tid];
        s_mem[tid] = acc;
    }

    int u = user_idx[b];
    const int* tibase = uti + (size_t)u * NS * NT;
    float bw = b_word[0];
    int half = lane >> 4;          // 0: even rows, 1: odd rows
    int il = lane & 15;            // owns dims [4il..4il+3] and [4(il+16)..]

    for (int h = 0; h < NHOOPS; h++) {
        __syncthreads();           // s_mem ready

        float4 ma = ((const float4*)s_mem)[il];
        float4 mb = ((const float4*)s_mem)[il + 16];

        // ---- word-level attention: warp w handles s = w, w+8, ... ----
        for (int s = warp; s < NS; s += 8) {
            const int* ti = tibase + s * NT;
            int idx = ti[lane];    // one coalesced load of all 32 indices

            float  ssum = 0.f;
            float4 aa = make_float4(0.f, 0.f, 0.f, 0.f);
            float4 ab = make_float4(0.f, 0.f, 0.f, 0.f);

#pragma unroll 8
            for (int p = 0; p < NT / 2; p++) {
                int w = __shfl_sync(0xffffffffu, idx, 2 * p + half);
                const float4* row = (const float4*)(emb_word + (size_t)w * ND);
                float4 va = row[il], vb = row[il + 16];
                float a = va.x * ma.x + va.y * ma.y + va.z * ma.z + va.w * ma.w
                        + vb.x * mb.x + vb.y * mb.y + vb.z * mb.z + vb.w * mb.w;
#pragma unroll
                for (int o = 8; o > 0; o >>= 1) a += __shfl_xor_sync(0xffffffffu, a, o);
                float e = __expf(a);
                aa.x += e * va.x; aa.y += e * va.y; aa.z += e * va.z; aa.w += e * va.w;
                ab.x += e * vb.x; ab.y += e * vb.y; ab.z += e * vb.z; ab.w += e * vb.w;
                ssum += e;
            }

            // combine even/odd-row halves (xor 16)
            float denom = ssum + __shfl_xor_sync(0xffffffffu, ssum, 16);
            aa.x += __shfl_xor_sync(0xffffffffu, aa.x, 16);
            aa.y += __shfl_xor_sync(0xffffffffu, aa.y, 16);
            aa.z += __shfl_xor_sync(0xffffffffu, aa.z, 16);
            aa.w += __shfl_xor_sync(0xffffffffu, aa.w, 16);
            ab.x += __shfl_xor_sync(0xffffffffu, ab.x, 16);
            ab.y += __shfl_xor_sync(0xffffffffu, ab.y, 16);
            ab.z += __shfl_xor_sync(0xffffffffu, ab.z, 16);
            ab.w += __shfl_xor_sync(0xffffffffu, ab.w, 16);

            float inv = 1.f / denom;
            float4 sa = make_float4(aa.x * inv, aa.y * inv, aa.z * inv, aa.w * inv);
            float4 sb = make_float4(ab.x * inv, ab.y * inv, ab.z * inv, ab.w * inv);

            ((float4*)(s_sent + s * ND))[il + half * 16] = half ? sb : sa;

            // sw[s] = sentence . w_word + b_word (16-lane reduce covers 128 dims)
            const float4* wp = (const float4*)w_word;
            float4 wa = wp[il], wb = wp[il + 16];
            float a = sa.x * wa.x + sa.y * wa.y + sa.z * wa.z + sa.w * wa.w
                    + sb.x * wb.x + sb.y * wb.y + sb.z * wb.z + sb.w * wb.w;
#pragma unroll
            for (int o = 8; o > 0; o >>= 1) a += __shfl_xor_sync(0xffffffffu, a, o);
            if (lane == 0) s_sw[s] = a + bw;
        }
        __syncthreads();

        // ---- sentence-level softmax (warp 0) ----
        if (warp == 0) {
            float4 m4 = ((const float4*)s_mem)[lane];
            float4 ws4 = ((const float4*)w_sent)[lane];
            float a = m4.x * ws4.x + m4.y * ws4.y + m4.z * ws4.z + m4.w * ws4.w;
#pragma unroll
            for (int o = 16; o > 0; o >>= 1) a += __shfl_xor_sync(0xffffffffu, a, o);
            float iw = a + b_sent[0];

            float x0 = tanhf(s_sw[lane] + iw);
            float x1 = (lane + 32 < NS) ? tanhf(s_sw[lane + 32] + iw) : -1e30f;
            float mx = fmaxf(x0, x1);
#pragma unroll
            for (int o = 16; o > 0; o >>= 1) mx = fmaxf(mx, __shfl_xor_sync(0xffffffffu, mx, o));
            float e0 = expf(x0 - mx);
            float e1 = (lane + 32 < NS) ? expf(x1 - mx) : 0.f;
            float sm = e0 + e1;
#pragma unroll
            for (int o = 16; o > 0; o >>= 1) sm += __shfl_xor_sync(0xffffffffu, sm, o);
            s_st[lane] = e0 / sm;
            if (lane + 32 < NS) s_st[lane + 32] = e1 / sm;
        }
        __syncthreads();

        // ---- mem += sum_s st[s] * sentence[s] ----
        if (tid < ND) {
            float acc = s_mem[tid];
#pragma unroll 10
            for (int s = 0; s < NS; s++) acc += s_st[s] * s_sent[s * ND + tid];
            s_mem[tid] = acc;
        }
    }

    __syncthreads();
    if (tid < ND) g_mem[b * ND + tid] = s_mem[tid];
}

// ============================================================================
// Kernel D: friends + group_idx + MLP gate + rating.
// ============================================================================
__device__ __forceinline__ float sigm(float x) { return 1.f / (1.f + expf(-x)); }

__global__ void k_final(const int* __restrict__ user_idx,
                        const float* __restrict__ emb_user,
                        const int* __restrict__ ufi,
                        const float* __restrict__ W_tr, const float* __restrict__ b_tr,
                        const float* __restrict__ W1, const float* __restrict__ b1,
                        const float* __restrict__ W2, const float* __restrict__ b2,
                        const float* __restrict__ W3, const float* __restrict__ b3,
                        const float* __restrict__ w_aff, const float* __restrict__ b_aff,
                        float* __restrict__ out_rating, float* __restrict__ out_group) {
    int b = blockIdx.x, tid = threadIdx.x, lane = tid & 31, warp = tid >> 5;
    __shared__ float s_mem[ND], s_item[NL], s_waff[NL];
    __shared__ float s_g[NCLIP];
    __shared__ int s_f[NCLIP];
    __shared__ float s_a1[32], s_a2[16], s_alpha[2];
    __shared__ float s_red[2];
    __shared__ float s_fn;

    s_mem[tid] = g_mem[b * ND + tid];
    s_mem[tid + 64] = g_mem[b * ND + tid + 64];
    s_item[tid] = g_item[b * NL + tid];
    s_waff[tid] = w_aff[tid];
    int u = user_idx[b];
    if (tid < NCLIP) s_f[tid] = ufi[(size_t)u * NCLIP + tid];
    __syncthreads();

    float ba = b_aff[0];

    float ept = b_tr[tid];
#pragma unroll 8
    for (int d = 0; d < ND; d++) ept += s_mem[d] * W_tr[d * NL + tid];

    for (int c = warp; c < NCLIP; c += 2) {
        const float* fr = emb_user + (size_t)s_f[c] * NL;
        float a = fr[lane] * s_item[lane] * s_waff[lane]
                + fr[lane + 32] * s_item[lane + 32] * s_waff[lane + 32];
#pragma unroll
        for (int o = 16; o > 0; o >>= 1) a += __shfl_down_sync(0xffffffffu, a, o);
        if (lane == 0) {
            float gi = sigm(a + ba);
            s_g[c] = gi;
            out_group[b * NCLIP + c] = gi;
        }
    }
    __syncthreads();

    if (tid == 0) {
        int cnt = 0;
        for (int c = 0; c < NCLIP; c++) cnt += (s_f[c] == NFR);
        s_fn = (float)(NCLIP - cnt);
    }

    float ue = 0.f;
    for (int c = 0; c < NCLIP; c++)
        ue += s_g[c] * emb_user[(size_t)s_f[c] * NL + tid];
    __syncthreads();
    ue /= s_fn;

    if (tid < 32) {
        float a = b1[tid];
#pragma unroll
        for (int k = 0; k < 64; k++) a += s_item[k] * W1[k * 32 + tid];
        s_a1[tid] = sigm(a);
    }
    __syncthreads();
    if (tid < 16) {
        float a = b2[tid];
#pragma unroll
        for (int k = 0; k < 32; k++) a += s_a1[k] * W2[k * 16 + tid];
        s_a2[tid] = sigm(a);
    }
    __syncthreads();
    if (tid < 2) {
        float a = b3[tid];
#pragma unroll
        for (int k = 0; k < 16; k++) a += s_a2[k] * W3[k * 2 + tid];
        s_alpha[tid] = sigm(a);
    }
    __syncthreads();

    float vec = s_alpha[0] * ept + s_alpha[1] * ue;
    float r = vec * s_item[tid] * s_waff[tid];
#pragma unroll
    for (int o = 16; o > 0; o >>= 1) r += __shfl_down_sync(0xffffffffu, r, o);
    if (lane == 0) s_red[warp] = r;
    __syncthreads();
    if (tid == 0) out_rating[b] = sigm(s_red[0] + s_red[1] + ba);
}

// ============================================================================
extern "C" void kernel_launch(void* const* d_in, const int* in_sizes, int n_in,
                              void* d_out, int out_size) {
    const int*   user_idx = (const int*)d_in[0];
    const int*   item_idx = (const int*)d_in[1];
    const float* emb_word = (const float*)d_in[2];
    const float* emb_item = (const float*)d_in[3];
    const float* emb_user = (const float*)d_in[4];
    const float* W_mem    = (const float*)d_in[5];
    const float* b_mem    = (const float*)d_in[6];
    const float* w_word   = (const float*)d_in[7];
    const float* b_word   = (const float*)d_in[8];
    const float* w_sent   = (const float*)d_in[9];
    const float* b_sent   = (const float*)d_in[10];
    const float* W_tr     = (const float*)d_in[11];
    const float* b_tr     = (const float*)d_in[12];
    const float* W1       = (const float*)d_in[13];
    const float* b1       = (const float*)d_in[14];
    const float* W2       = (const float*)d_in[15];
    const float* b2       = (const float*)d_in[16];
    const float* W3       = (const float*)d_in[17];
    const float* b3       = (const float*)d_in[18];
    const float* w_aff    = (const float*)d_in[19];
    const float* b_aff    = (const float*)d_in[20];
    const int*   uti      = (const int*)d_in[21];
    const int*   ufi      = (const int*)d_in[22];
    float* out = (float*)d_out;

    k_hoops<<<NB, 256>>>(user_idx, item_idx, emb_item, W_mem, b_mem,
                         uti, emb_word, w_word, b_word, w_sent, b_sent);
    k_final<<<NB, 64>>>(user_idx, emb_user, ufi, W_tr, b_tr,
                        W1, b1, W2, b2, W3, b3, w_aff, b_aff,
                        out, out + NB);
}

// round 17
// speedup vs baseline: 1.6276x; 1.6276x over previous
#include <cuda_runtime.h>

#define NB 512
#define ND 128
#define NS 50
#define NT 32
#define NHOOPS 2
#define NL 64
#define NCLIP 50
#define NFR 10000

// ---- scratch (static device globals; no runtime allocation) ----
__device__ float g_mem[NB * ND];            // [B, D]
__device__ float g_item[NB * NL];           // [B, L]
__device__ float g_sentence[NB * NS * ND];  // [B, S, D]
__device__ float g_sw[NB * NS];             // [B, S]

// ============================================================================
// Kernel A: item_emb gather + mem = item_emb @ W_mem + b_mem
// ============================================================================
__global__ void k_init(const int* __restrict__ item_idx,
                       const float* __restrict__ emb_item,
                       const float* __restrict__ W_mem,
                       const float* __restrict__ b_mem) {
    int b = blockIdx.x, tid = threadIdx.x;
    __shared__ float s_it[NL];
    int it = item_idx[b];
    if (tid < NL) {
        float v = emb_item[(size_t)it * NL + tid];
        s_it[tid] = v;
        g_item[b * NL + tid] = v;
    }
    __syncthreads();
    float acc = b_mem[tid];
#pragma unroll
    for (int l = 0; l < NL; l++) acc += s_it[l] * W_mem[l * ND + tid];
    g_mem[b * ND + tid] = acc;
}

// ============================================================================
// Kernel B (R12 config — best known): warp per (b,s), half-warp per row,
// un-shifted softmax, unroll 8, no launch bounds.
// ============================================================================
__global__ void k_word(const int* __restrict__ user_idx,
                       const int* __restrict__ uti,
                       const float* __restrict__ emb_word,
                       const float* __restrict__ w_word,
                       const float* __restrict__ b_word) {
    int wg = (blockIdx.x * blockDim.x + threadIdx.x) >> 5;   // 0 .. B*S-1
    int lane = threadIdx.x & 31;
    int b = wg / NS, s = wg % NS;
    int half = lane >> 4;
    int il = lane & 15;

    const float4* memp = (const float4*)(g_mem + (size_t)b * ND);
    float4 ma = memp[il], mb = memp[il + 16];

    int u = user_idx[b];
    const int* ti = uti + ((size_t)u * NS + s) * NT;
    int idx = ti[lane];

    float  ssum = 0.f;
    float4 aa = make_float4(0.f, 0.f, 0.f, 0.f);
    float4 ab = make_float4(0.f, 0.f, 0.f, 0.f);

#pragma unroll 8
    for (int p = 0; p < NT / 2; p++) {
        int w = __shfl_sync(0xffffffffu, idx, 2 * p + half);
        const float4* row = (const float4*)(emb_word + (size_t)w * ND);
        float4 va = row[il], vb = row[il + 16];
        float a = va.x * ma.x + va.y * ma.y + va.z * ma.z + va.w * ma.w
                + vb.x * mb.x + vb.y * mb.y + vb.z * mb.z + vb.w * mb.w;
#pragma unroll
        for (int o = 8; o > 0; o >>= 1) a += __shfl_xor_sync(0xffffffffu, a, o);
        float e = __expf(a);
        aa.x += e * va.x; aa.y += e * va.y; aa.z += e * va.z; aa.w += e * va.w;
        ab.x += e * vb.x; ab.y += e * vb.y; ab.z += e * vb.z; ab.w += e * vb.w;
        ssum += e;
    }

    float denom = ssum + __shfl_xor_sync(0xffffffffu, ssum, 16);
    aa.x += __shfl_xor_sync(0xffffffffu, aa.x, 16);
    aa.y += __shfl_xor_sync(0xffffffffu, aa.y, 16);
    aa.z += __shfl_xor_sync(0xffffffffu, aa.z, 16);
    aa.w += __shfl_xor_sync(0xffffffffu, aa.w, 16);
    ab.x += __shfl_xor_sync(0xffffffffu, ab.x, 16);
    ab.y += __shfl_xor_sync(0xffffffffu, ab.y, 16);
    ab.z += __shfl_xor_sync(0xffffffffu, ab.z, 16);
    ab.w += __shfl_xor_sync(0xffffffffu, ab.w, 16);

    float inv = 1.f / denom;
    float4 sa = make_float4(aa.x * inv, aa.y * inv, aa.z * inv, aa.w * inv);
    float4 sb = make_float4(ab.x * inv, ab.y * inv, ab.z * inv, ab.w * inv);

    float4* sentp = (float4*)(g_sentence + (size_t)wg * ND);
    sentp[il + half * 16] = half ? sb : sa;

    const float4* wp = (const float4*)w_word;
    float4 wa = wp[il], wb = wp[il + 16];
    float a = sa.x * wa.x + sa.y * wa.y + sa.z * wa.z + sa.w * wa.w
            + sb.x * wb.x + sb.y * wb.y + sb.z * wb.z + sb.w * wb.w;
#pragma unroll
    for (int o = 8; o > 0; o >>= 1) a += __shfl_xor_sync(0xffffffffu, a, o);
    if (lane == 0) g_sw[wg] = a + b_word[0];
}

// ============================================================================
// Kernel C: sentence-level attention + memory update for one b.
// ============================================================================
__global__ void k_sent(const float* __restrict__ w_sent,
                       const float* __restrict__ b_sent) {
    int b = blockIdx.x, tid = threadIdx.x, lane = tid & 31, warp = tid >> 5;
    __shared__ float st[NS];
    __shared__ __align__(16) float4 s_part[3][32];

    float4 mv4;
    if (warp == 0) {
        mv4 = ((const float4*)(g_mem + (size_t)b * ND))[lane];
        float4 ws4 = ((const float4*)w_sent)[lane];
        float a = mv4.x * ws4.x + mv4.y * ws4.y + mv4.z * ws4.z + mv4.w * ws4.w;
#pragma unroll
        for (int o = 16; o > 0; o >>= 1) a += __shfl_xor_sync(0xffffffffu, a, o);
        float iw = a + b_sent[0];

        float x0 = tanhf(g_sw[b * NS + lane] + iw);
        float x1 = (lane + 32 < NS) ? tanhf(g_sw[b * NS + lane + 32] + iw) : -1e30f;
        float mx = fmaxf(x0, x1);
#pragma unroll
        for (int o = 16; o > 0; o >>= 1) mx = fmaxf(mx, __shfl_xor_sync(0xffffffffu, mx, o));
        float e0 = expf(x0 - mx);
        float e1 = (lane + 32 < NS) ? expf(x1 - mx) : 0.f;
        float sm = e0 + e1;
#pragma unroll
        for (int o = 16; o > 0; o >>= 1) sm += __shfl_xor_sync(0xffffffffu, sm, o);
        st[lane] = e0 / sm;
        if (lane + 32 < NS) st[lane + 32] = e1 / sm;
    }
    __syncthreads();

    float4 acc = make_float4(0.f, 0.f, 0.f, 0.f);
    const float4* sent = (const float4*)(g_sentence + (size_t)b * NS * ND);
    for (int s = warp; s < NS; s += 4) {
        float wgt = st[s];
        float4 v = sent[s * 32 + lane];
        acc.x += wgt * v.x; acc.y += wgt * v.y;
        acc.z += wgt * v.z; acc.w += wgt * v.w;
    }
    if (warp > 0) s_part[warp - 1][lane] = acc;
    __syncthreads();

    if (warp == 0) {
        float4 p0 = s_part[0][lane], p1 = s_part[1][lane], p2 = s_part[2][lane];
        mv4.x += acc.x + p0.x + p1.x + p2.x;
        mv4.y += acc.y + p0.y + p1.y + p2.y;
        mv4.z += acc.z + p0.z + p1.z + p2.z;
        mv4.w += acc.w + p0.w + p1.w + p2.w;
        ((float4*)(g_mem + (size_t)b * ND))[lane] = mv4;
    }
}

// ============================================================================
// Kernel D (REWRITTEN, 256 threads): friends + group_idx + MLP gate + rating.
// ept: 4-way split GEMV (thread (c,l), 32-iter chains, coalesced over l).
// group_idx: 8 warps over 50 friends. user_emb: 4-way split over friends.
// ============================================================================
__device__ __forceinline__ float sigm(float x) { return 1.f / (1.f + expf(-x)); }

__global__ void __launch_bounds__(256)
k_final(const int* __restrict__ user_idx,
        const float* __restrict__ emb_user,
        const int* __restrict__ ufi,
        const float* __restrict__ W_tr, const float* __restrict__ b_tr,
        const float* __restrict__ W1, const float* __restrict__ b1,
        const float* __restrict__ W2, const float* __restrict__ b2,
        const float* __restrict__ W3, const float* __restrict__ b3,
        const float* __restrict__ w_aff, const float* __restrict__ b_aff,
        float* __restrict__ out_rating, float* __restrict__ out_group) {
    int b = blockIdx.x, tid = threadIdx.x, lane = tid & 31, warp = tid >> 5;
    int l = tid & 63, quad = tid >> 6;          // quad = 0..3

    __shared__ float s_mem[ND], s_item[NL], s_waff[NL];
    __shared__ float s_g[NCLIP];
    __shared__ int s_f[NCLIP];
    __shared__ float s_part[4][NL];             // ept partials / user_emb partials
    __shared__ float s_ept[NL];
    __shared__ float s_a1[32], s_a2[16], s_alpha[2];
    __shared__ float s_red[2];
    __shared__ float s_fn;

    if (tid < ND) s_mem[tid] = g_mem[b * ND + tid];
    if (tid >= ND && tid < ND + NL) s_item[tid - ND] = g_item[b * NL + tid - ND];
    if (tid >= 192 && tid < 192 + NL) s_waff[tid - 192] = w_aff[tid - 192];
    int u = user_idx[b];
    __syncthreads();
    if (tid < NCLIP) s_f[tid] = ufi[(size_t)u * NCLIP + tid];
    __syncthreads();

    float ba = b_aff[0];

    // ---- ept = mem @ W_tr + b_tr : quad q covers dims [32q, 32q+32) ----
    {
        float p = 0.f;
        int d0 = quad * 32;
#pragma unroll 8
        for (int d = 0; d < 32; d++)
            p += s_mem[d0 + d] * W_tr[(d0 + d) * NL + l];
        s_part[quad][l] = p;
    }

    // ---- group_idx: warp w handles friends c = w, w+8, ... ----
    for (int c = warp; c < NCLIP; c += 8) {
        const float* fr = emb_user + (size_t)s_f[c] * NL;
        float a = fr[lane] * s_item[lane] * s_waff[lane]
                + fr[lane + 32] * s_item[lane + 32] * s_waff[lane + 32];
#pragma unroll
        for (int o = 16; o > 0; o >>= 1) a += __shfl_down_sync(0xffffffffu, a, o);
        if (lane == 0) {
            float gi = sigm(a + ba);
            s_g[c] = gi;
            out_group[b * NCLIP + c] = gi;
        }
    }
    if (tid == 0) {
        int cnt = 0;
#pragma unroll
        for (int c = 0; c < NCLIP; c++) cnt += (s_f[c] == NFR);
        s_fn = (float)(NCLIP - cnt);
    }
    __syncthreads();

    // finalize ept
    if (tid < NL)
        s_ept[tid] = b_tr[tid] + s_part[0][tid] + s_part[1][tid]
                   + s_part[2][tid] + s_part[3][tid];

    // ---- user_emb: quad q covers friends c ≡ q (mod 4) ----
    {
        float p = 0.f;
        for (int c = quad; c < NCLIP; c += 4)
            p += s_g[c] * emb_user[(size_t)s_f[c] * NL + l];
        __syncthreads();          // s_part free (ept consumed)
        s_part[quad][l] = p;
    }
    __syncthreads();

    // ---- gating MLP: 64 -> 32 -> 16 -> 2 ----
    if (tid < 32) {
        float a = b1[tid];
#pragma unroll
        for (int k = 0; k < 64; k++) a += s_item[k] * W1[k * 32 + tid];
        s_a1[tid] = sigm(a);
    }
    __syncthreads();
    if (tid < 16) {
        float a = b2[tid];
#pragma unroll
        for (int k = 0; k < 32; k++) a += s_a1[k] * W2[k * 16 + tid];
        s_a2[tid] = sigm(a);
    }
    __syncthreads();
    if (tid < 2) {
        float a = b3[tid];
#pragma unroll
        for (int k = 0; k < 16; k++) a += s_a2[k] * W3[k * 2 + tid];
        s_alpha[tid] = sigm(a);
    }
    __syncthreads();

    // ---- rating (threads 0..63, warps 0-1) ----
    if (tid < NL) {
        float ue = (s_part[0][tid] + s_part[1][tid] + s_part[2][tid] + s_part[3][tid]) / s_fn;
        float vec = s_alpha[0] * s_ept[tid] + s_alpha[1] * ue;
        float r = vec * s_item[tid] * s_waff[tid];
#pragma unroll
        for (int o = 16; o > 0; o >>= 1) r += __shfl_down_sync(0xffffffffu, r, o);
        if (lane == 0) s_red[warp] = r;
    }
    __syncthreads();
    if (tid == 0) out_rating[b] = sigm(s_red[0] + s_red[1] + ba);
}

// ============================================================================
extern "C" void kernel_launch(void* const* d_in, const int* in_sizes, int n_in,
                              void* d_out, int out_size) {
    const int*   user_idx = (const int*)d_in[0];
    const int*   item_idx = (const int*)d_in[1];
    const float* emb_word = (const float*)d_in[2];
    const float* emb_item = (const float*)d_in[3];
    const float* emb_user = (const float*)d_in[4];
    const float* W_mem    = (const float*)d_in[5];
    const float* b_mem    = (const float*)d_in[6];
    const float* w_word   = (const float*)d_in[7];
    const float* b_word   = (const float*)d_in[8];
    const float* w_sent   = (const float*)d_in[9];
    const float* b_sent   = (const float*)d_in[10];
    const float* W_tr     = (const float*)d_in[11];
    const float* b_tr     = (const float*)d_in[12];
    const float* W1       = (const float*)d_in[13];
    const float* b1       = (const float*)d_in[14];
    const float* W2       = (const float*)d_in[15];
    const float* b2       = (const float*)d_in[16];
    const float* W3       = (const float*)d_in[17];
    const float* b3       = (const float*)d_in[18];
    const float* w_aff    = (const float*)d_in[19];
    const float* b_aff    = (const float*)d_in[20];
    const int*   uti      = (const int*)d_in[21];
    const int*   ufi      = (const int*)d_in[22];
    float* out = (float*)d_out;

    k_init<<<NB, ND>>>(item_idx, emb_item, W_mem, b_mem);
    int wblocks = (NB * NS) / 8;     // 8 warps per block
    for (int h = 0; h < NHOOPS; h++) {
        k_word<<<wblocks, 256>>>(user_idx, uti, emb_word, w_word, b_word);
        k_sent<<<NB, 128>>>(w_sent, b_sent);
    }
    k_final<<<NB, 256>>>(user_idx, emb_user, ufi, W_tr, b_tr,
                         W1, b1, W2, b2, W3, b3, w_aff, b_aff,
                         out, out + NB);
}